// round 2
// baseline (speedup 1.0000x reference)
#include <cuda_runtime.h>
#include <cuda_bf16.h>
#include <cstdint>

// Problem dims
#define NTOK   32768           // B*S = 4*8192
#define DMODEL 1024
#define NCOMP  5
#define LN_EPS 1e-5f

// ---------------- scratch (device globals; no allocation allowed) ----------
__device__ __nv_bfloat16 g_yhi[(size_t)NTOK * DMODEL];   // 64 MB
__device__ __nv_bfloat16 g_ylo[(size_t)NTOK * DMODEL];   // 64 MB
__device__ __nv_bfloat16 g_whi[DMODEL * DMODEL];         // 2 MB  (W + I, hi)
__device__ __nv_bfloat16 g_wlo[DMODEL * DMODEL];         // 2 MB  (W + I, lo)

// ---------------- PTX helpers ----------------------------------------------
__device__ __forceinline__ uint32_t smem_u32(const void* p) {
    uint32_t a;
    asm("{ .reg .u64 t; cvta.to.shared.u64 t, %1; cvt.u32.u64 %0, t; }"
        : "=r"(a) : "l"(p));
    return a;
}

#define CP_ASYNC16(dst, src) \
    asm volatile("cp.async.cg.shared.global [%0], [%1], 16;" \
                 :: "r"(dst), "l"(src))
#define CP_COMMIT() asm volatile("cp.async.commit_group;" ::: "memory")
#define CP_WAIT1()  asm volatile("cp.async.wait_group 1;" ::: "memory")

__device__ __forceinline__ void ldsm_x4(uint32_t* r, uint32_t addr) {
    asm volatile("ldmatrix.sync.aligned.m8n8.x4.shared.b16 {%0,%1,%2,%3}, [%4];"
                 : "=r"(r[0]), "=r"(r[1]), "=r"(r[2]), "=r"(r[3]) : "r"(addr));
}

__device__ __forceinline__ void mma_16816(float* c, const uint32_t* a,
                                          uint32_t b0, uint32_t b1) {
    asm volatile(
        "mma.sync.aligned.m16n8k16.row.col.f32.bf16.bf16.f32 "
        "{%0,%1,%2,%3}, {%4,%5,%6,%7}, {%8,%9}, {%0,%1,%2,%3};\n"
        : "+f"(c[0]), "+f"(c[1]), "+f"(c[2]), "+f"(c[3])
        : "r"(a[0]), "r"(a[1]), "r"(a[2]), "r"(a[3]), "r"(b0), "r"(b1));
}

// ---------------- Kernel 1: fused LayerNorm + affine + bf16 hi/lo split ----
__global__ __launch_bounds__(256)
void ln_split_kernel(const float* __restrict__ x, const int* __restrict__ ids,
                     const float* __restrict__ gamma, const float* __restrict__ beta,
                     const float* __restrict__ scale) {
    const int token = blockIdx.x;
    const int tid = threadIdx.x;
    const int wid = tid >> 5, lid = tid & 31;
    const float* xr = x + (size_t)token * DMODEL;

    float4 v = *reinterpret_cast<const float4*>(xr + tid * 4);
    float s1 = v.x + v.y + v.z + v.w;
    float s2 = v.x * v.x + v.y * v.y + v.z * v.z + v.w * v.w;
#pragma unroll
    for (int o = 16; o > 0; o >>= 1) {
        s1 += __shfl_xor_sync(0xffffffffu, s1, o);
        s2 += __shfl_xor_sync(0xffffffffu, s2, o);
    }
    __shared__ float r1[8], r2[8];
    if (lid == 0) { r1[wid] = s1; r2[wid] = s2; }
    __syncthreads();
    float t1 = 0.f, t2 = 0.f;
#pragma unroll
    for (int i = 0; i < 8; i++) { t1 += r1[i]; t2 += r2[i]; }
    const float mu = t1 * (1.0f / DMODEL);
    const float var = t2 * (1.0f / DMODEL) - mu * mu;
    const float rsig = rsqrtf(var + LN_EPS);

    const int cr = ids[token];
    const bool valid = (cr < NCOMP);
    const int cid = cr < 0 ? 0 : (cr >= NCOMP ? NCOMP - 1 : cr);
    const float sc = scale[cid];
    const float4 g4 = *reinterpret_cast<const float4*>(gamma + cid * DMODEL + tid * 4);
    const float4 b4 = *reinterpret_cast<const float4*>(beta + cid * DMODEL + tid * 4);

    float y0, y1, y2, y3;
    if (valid) {
        y0 = ((v.x - mu) * rsig * g4.x + b4.x) * sc;
        y1 = ((v.y - mu) * rsig * g4.y + b4.y) * sc;
        y2 = ((v.z - mu) * rsig * g4.z + b4.z) * sc;
        y3 = ((v.w - mu) * rsig * g4.w + b4.w) * sc;
    } else {
        y0 = v.x; y1 = v.y; y2 = v.z; y3 = v.w;
    }

    __nv_bfloat16 h0 = __float2bfloat16(y0), h1 = __float2bfloat16(y1);
    __nv_bfloat16 h2 = __float2bfloat16(y2), h3 = __float2bfloat16(y3);
    __nv_bfloat16 l0 = __float2bfloat16(y0 - __bfloat162float(h0));
    __nv_bfloat16 l1 = __float2bfloat16(y1 - __bfloat162float(h1));
    __nv_bfloat16 l2 = __float2bfloat16(y2 - __bfloat162float(h2));
    __nv_bfloat16 l3 = __float2bfloat16(y3 - __bfloat162float(h3));

    const size_t base = (size_t)token * DMODEL + tid * 4;
    *reinterpret_cast<__nv_bfloat162*>(g_yhi + base)     = __halves2bfloat162(h0, h1);
    *reinterpret_cast<__nv_bfloat162*>(g_yhi + base + 2) = __halves2bfloat162(h2, h3);
    *reinterpret_cast<__nv_bfloat162*>(g_ylo + base)     = __halves2bfloat162(l0, l1);
    *reinterpret_cast<__nv_bfloat162*>(g_ylo + base + 2) = __halves2bfloat162(l2, l3);
}

// ---------------- Kernel 2: (W + I) bf16 hi/lo split ------------------------
__global__ __launch_bounds__(256)
void wsplit_kernel(const float* __restrict__ W) {
    const int idx = (blockIdx.x * 256 + threadIdx.x) * 4;
    const int row = idx >> 10;          // DMODEL = 1024
    const int col = idx & 1023;
    float4 v = *reinterpret_cast<const float4*>(W + idx);
    // fold identity: out = y*(W^T) + y  ==  y * (W + I)^T   (W'[n][k] = W[n][k] + (n==k))
    if (row == col + 0) v.x += 1.0f;
    if (row == col + 1) v.y += 1.0f;
    if (row == col + 2) v.z += 1.0f;
    if (row == col + 3) v.w += 1.0f;
    __nv_bfloat16 h0 = __float2bfloat16(v.x), h1 = __float2bfloat16(v.y);
    __nv_bfloat16 h2 = __float2bfloat16(v.z), h3 = __float2bfloat16(v.w);
    __nv_bfloat16 l0 = __float2bfloat16(v.x - __bfloat162float(h0));
    __nv_bfloat16 l1 = __float2bfloat16(v.y - __bfloat162float(h1));
    __nv_bfloat16 l2 = __float2bfloat16(v.z - __bfloat162float(h2));
    __nv_bfloat16 l3 = __float2bfloat16(v.w - __bfloat162float(h3));
    *reinterpret_cast<__nv_bfloat162*>(g_whi + idx)     = __halves2bfloat162(h0, h1);
    *reinterpret_cast<__nv_bfloat162*>(g_whi + idx + 2) = __halves2bfloat162(h2, h3);
    *reinterpret_cast<__nv_bfloat162*>(g_wlo + idx)     = __halves2bfloat162(l0, l1);
    *reinterpret_cast<__nv_bfloat162*>(g_wlo + idx + 2) = __halves2bfloat162(l2, l3);
}

// ---------------- Kernel 3: bf16x3 mma.sync GEMM, out = y*W'^T + b ----------
#define BM 128
#define BN 128
#define BK 64
#define TILE_B  16384                 // 128 rows * 128B (64 bf16 / row, SW128)
#define STAGE_B (4 * TILE_B)          // Ahi, Alo, Bhi, Blo
#define STAGES 3
#define GEMM_SMEM (STAGES * STAGE_B)  // 192 KB

__device__ __forceinline__ int sw128(int off) {
    return off ^ ((off >> 3) & 0x70);
}

__global__ __launch_bounds__(256, 1)
void gemm_kernel(const float* __restrict__ bvec, float* __restrict__ out) {
    extern __shared__ char smem[];
    const int tid = threadIdx.x;
    const int wid = tid >> 5, lane = tid & 31;
    const int m_tile = blockIdx.x >> 3;           // 256 m tiles
    const int n_tile = blockIdx.x & 7;            // 8 n tiles (inner -> A L2 reuse)
    const int m_base = m_tile * BM, n_base = n_tile * BN;
    const int warp_m = (wid & 3) * 32;            // 4 warps along m
    const int warp_n = (wid >> 2) * 64;           // 2 warps along n

    const __nv_bfloat16* srcA0 = g_yhi + (size_t)m_base * DMODEL;
    const __nv_bfloat16* srcA1 = g_ylo + (size_t)m_base * DMODEL;
    const __nv_bfloat16* srcB0 = g_whi + (size_t)n_base * DMODEL;
    const __nv_bfloat16* srcB1 = g_wlo + (size_t)n_base * DMODEL;

    auto load_stage = [&](int slot, int kc) {
        const int koff = kc * BK;
        char* sbase = smem + slot * STAGE_B;
        const __nv_bfloat16* srcs[4] = { srcA0 + koff, srcA1 + koff,
                                         srcB0 + koff, srcB1 + koff };
#pragma unroll
        for (int t = 0; t < 4; t++) {
#pragma unroll
            for (int i = 0; i < 4; i++) {
                const int seg_id = tid + i * 256;         // 0..1023
                const int row = seg_id >> 3, seg = seg_id & 7;
                const int off = sw128(row * 128 + seg * 16);
                const uint32_t dst = smem_u32(sbase + t * TILE_B + off);
                CP_ASYNC16(dst, srcs[t] + (size_t)row * DMODEL + seg * 8);
            }
        }
    };

    float acc[2][8][4];
#pragma unroll
    for (int mt = 0; mt < 2; mt++)
#pragma unroll
        for (int nt = 0; nt < 8; nt++)
#pragma unroll
            for (int i = 0; i < 4; i++) acc[mt][nt][i] = 0.0f;

    load_stage(0, 0); CP_COMMIT();
    load_stage(1, 1); CP_COMMIT();

    const int lrow = lane & 15, lhalf = lane >> 4;

#pragma unroll 1
    for (int kc = 0; kc < 16; kc++) {
        CP_WAIT1();                    // stage kc ready
        __syncthreads();
        if (kc + 2 < 16) load_stage((kc + 2) % STAGES, kc + 2);
        CP_COMMIT();                   // keep group count consistent

        const uint32_t st = smem_u32(smem + (kc % STAGES) * STAGE_B);
        const uint32_t aHiB = st, aLoB = st + TILE_B;
        const uint32_t bHiB = st + 2 * TILE_B, bLoB = st + 3 * TILE_B;

#pragma unroll
        for (int ks = 0; ks < 4; ks++) {
            uint32_t ah[2][4], al[2][4], bh4[4][4], bl4[4][4];
#pragma unroll
            for (int mt = 0; mt < 2; mt++) {
                const int row = warp_m + mt * 16 + lrow;
                const int off = sw128(row * 128 + (ks * 2 + lhalf) * 16);
                ldsm_x4(ah[mt], aHiB + off);
                ldsm_x4(al[mt], aLoB + off);
            }
#pragma unroll
            for (int np = 0; np < 4; np++) {
                const int row = warp_n + np * 16 + lrow;
                const int off = sw128(row * 128 + (ks * 2 + lhalf) * 16);
                ldsm_x4(bh4[np], bHiB + off);
                ldsm_x4(bl4[np], bLoB + off);
            }
#pragma unroll
            for (int mt = 0; mt < 2; mt++) {
#pragma unroll
                for (int nt = 0; nt < 8; nt++) {
                    const uint32_t h0 = bh4[nt >> 1][nt & 1];
                    const uint32_t h1 = bh4[nt >> 1][(nt & 1) + 2];
                    const uint32_t l0 = bl4[nt >> 1][nt & 1];
                    const uint32_t l1 = bl4[nt >> 1][(nt & 1) + 2];
                    mma_16816(acc[mt][nt], ah[mt], h0, h1);
                    mma_16816(acc[mt][nt], ah[mt], l0, l1);
                    mma_16816(acc[mt][nt], al[mt], h0, h1);
                }
            }
        }
        __syncthreads();
    }

    // ---- epilogue: out = acc + b[n] ----
    const int gID = lane >> 2, tig = lane & 3;
#pragma unroll
    for (int mt = 0; mt < 2; mt++) {
#pragma unroll
        for (int nt = 0; nt < 8; nt++) {
            const int n = n_base + warp_n + nt * 8 + tig * 2;
            const float b0 = bvec[n], b1 = bvec[n + 1];
            const int m0 = m_base + warp_m + mt * 16 + gID;
            float2 v0 = { acc[mt][nt][0] + b0, acc[mt][nt][1] + b1 };
            float2 v1 = { acc[mt][nt][2] + b0, acc[mt][nt][3] + b1 };
            *reinterpret_cast<float2*>(out + (size_t)m0 * DMODEL + n) = v0;
            *reinterpret_cast<float2*>(out + (size_t)(m0 + 8) * DMODEL + n) = v1;
        }
    }
}

// ---------------- launch ----------------------------------------------------
extern "C" void kernel_launch(void* const* d_in, const int* in_sizes, int n_in,
                              void* d_out, int out_size) {
    const float* x     = (const float*)d_in[0];
    const int*   ids   = (const int*)d_in[1];
    const float* gamma = (const float*)d_in[2];
    const float* beta  = (const float*)d_in[3];
    const float* scale = (const float*)d_in[4];
    const float* W     = (const float*)d_in[5];
    const float* bias  = (const float*)d_in[6];
    float* out = (float*)d_out;

    ln_split_kernel<<<NTOK, 256>>>(x, ids, gamma, beta, scale);
    wsplit_kernel<<<(DMODEL * DMODEL) / (256 * 4), 256>>>(W);

    cudaFuncSetAttribute(gemm_kernel,
                         cudaFuncAttributeMaxDynamicSharedMemorySize, GEMM_SMEM);
    gemm_kernel<<<(NTOK / BM) * (DMODEL / BN), 256, GEMM_SMEM>>>(bias, out);
}

// round 3
// speedup vs baseline: 1.4619x; 1.4619x over previous
#include <cuda_runtime.h>
#include <cuda_fp16.h>
#include <cstdint>

// Problem dims
#define NTOK   32768           // B*S = 4*8192
#define DMODEL 1024
#define NCOMP  5
#define LN_EPS 1e-5f

// ---------------- scratch (device globals; no allocation allowed) ----------
__device__ __half g_yh[(size_t)NTOK * DMODEL];   // 64 MB   y (fp16 hi)
__device__ __half g_wh[DMODEL * DMODEL];         // 2 MB    (W + I) hi
__device__ __half g_wl[DMODEL * DMODEL];         // 2 MB    (W + I) lo

// ---------------- PTX helpers ----------------------------------------------
__device__ __forceinline__ uint32_t smem_u32(const void* p) {
    uint32_t a;
    asm("{ .reg .u64 t; cvta.to.shared.u64 t, %1; cvt.u32.u64 %0, t; }"
        : "=r"(a) : "l"(p));
    return a;
}

#define CP_ASYNC16(dst, src) \
    asm volatile("cp.async.cg.shared.global [%0], [%1], 16;" \
                 :: "r"(dst), "l"(src))
#define CP_COMMIT() asm volatile("cp.async.commit_group;" ::: "memory")
#define CP_WAIT1()  asm volatile("cp.async.wait_group 1;" ::: "memory")

__device__ __forceinline__ void ldsm_x4(uint32_t* r, uint32_t addr) {
    asm volatile("ldmatrix.sync.aligned.m8n8.x4.shared.b16 {%0,%1,%2,%3}, [%4];"
                 : "=r"(r[0]), "=r"(r[1]), "=r"(r[2]), "=r"(r[3]) : "r"(addr));
}

__device__ __forceinline__ void mma_16816(float* c, const uint32_t* a,
                                          uint32_t b0, uint32_t b1) {
    asm volatile(
        "mma.sync.aligned.m16n8k16.row.col.f32.f16.f16.f32 "
        "{%0,%1,%2,%3}, {%4,%5,%6,%7}, {%8,%9}, {%0,%1,%2,%3};\n"
        : "+f"(c[0]), "+f"(c[1]), "+f"(c[2]), "+f"(c[3])
        : "r"(a[0]), "r"(a[1]), "r"(a[2]), "r"(a[3]), "r"(b0), "r"(b1));
}

// ---------------- Kernel 1: fused LayerNorm + affine -> fp16 ---------------
__global__ __launch_bounds__(256)
void ln_split_kernel(const float* __restrict__ x, const int* __restrict__ ids,
                     const float* __restrict__ gamma, const float* __restrict__ beta,
                     const float* __restrict__ scale) {
    const int token = blockIdx.x;
    const int tid = threadIdx.x;
    const int wid = tid >> 5, lid = tid & 31;
    const float* xr = x + (size_t)token * DMODEL;

    float4 v = *reinterpret_cast<const float4*>(xr + tid * 4);
    float s1 = v.x + v.y + v.z + v.w;
    float s2 = v.x * v.x + v.y * v.y + v.z * v.z + v.w * v.w;
#pragma unroll
    for (int o = 16; o > 0; o >>= 1) {
        s1 += __shfl_xor_sync(0xffffffffu, s1, o);
        s2 += __shfl_xor_sync(0xffffffffu, s2, o);
    }
    __shared__ float r1[8], r2[8];
    if (lid == 0) { r1[wid] = s1; r2[wid] = s2; }
    __syncthreads();
    float t1 = 0.f, t2 = 0.f;
#pragma unroll
    for (int i = 0; i < 8; i++) { t1 += r1[i]; t2 += r2[i]; }
    const float mu = t1 * (1.0f / DMODEL);
    const float var = t2 * (1.0f / DMODEL) - mu * mu;
    const float rsig = rsqrtf(var + LN_EPS);

    const int cr = ids[token];
    const bool valid = (cr < NCOMP);
    const int cid = cr < 0 ? 0 : (cr >= NCOMP ? NCOMP - 1 : cr);
    const float sc = scale[cid];
    const float4 g4 = *reinterpret_cast<const float4*>(gamma + cid * DMODEL + tid * 4);
    const float4 b4 = *reinterpret_cast<const float4*>(beta + cid * DMODEL + tid * 4);

    float y0, y1, y2, y3;
    if (valid) {
        y0 = ((v.x - mu) * rsig * g4.x + b4.x) * sc;
        y1 = ((v.y - mu) * rsig * g4.y + b4.y) * sc;
        y2 = ((v.z - mu) * rsig * g4.z + b4.z) * sc;
        y3 = ((v.w - mu) * rsig * g4.w + b4.w) * sc;
    } else {
        y0 = v.x; y1 = v.y; y2 = v.z; y3 = v.w;
    }

    const size_t base = (size_t)token * DMODEL + tid * 4;
    *reinterpret_cast<__half2*>(g_yh + base) =
        __floats2half2_rn(y0, y1);
    *reinterpret_cast<__half2*>(g_yh + base + 2) =
        __floats2half2_rn(y2, y3);
}

// ---------------- Kernel 2: (W + I) fp16 hi/lo split ------------------------
__global__ __launch_bounds__(256)
void wsplit_kernel(const float* __restrict__ W) {
    const int idx = (blockIdx.x * 256 + threadIdx.x) * 4;
    const int row = idx >> 10;          // DMODEL = 1024
    const int col = idx & 1023;
    float4 v = *reinterpret_cast<const float4*>(W + idx);
    // fold residual: out = y*W^T + y  ==  y*(W + I)^T   (W'[n][k] = W[n][k] + (n==k))
    if (row == col + 0) v.x += 1.0f;
    if (row == col + 1) v.y += 1.0f;
    if (row == col + 2) v.z += 1.0f;
    if (row == col + 3) v.w += 1.0f;
    __half h0 = __float2half_rn(v.x), h1 = __float2half_rn(v.y);
    __half h2 = __float2half_rn(v.z), h3 = __float2half_rn(v.w);
    __half l0 = __float2half_rn(v.x - __half2float(h0));
    __half l1 = __float2half_rn(v.y - __half2float(h1));
    __half l2 = __float2half_rn(v.z - __half2float(h2));
    __half l3 = __float2half_rn(v.w - __half2float(h3));
    *reinterpret_cast<__half2*>(g_wh + idx)     = __halves2half2(h0, h1);
    *reinterpret_cast<__half2*>(g_wh + idx + 2) = __halves2half2(h2, h3);
    *reinterpret_cast<__half2*>(g_wl + idx)     = __halves2half2(l0, l1);
    *reinterpret_cast<__half2*>(g_wl + idx + 2) = __halves2half2(l2, l3);
}

// ---------------- Kernel 3: fp16x2 mma.sync GEMM, out = yh*W'^T + b ---------
#define BM 128
#define BN 128
#define BK 64
#define TILE_B  16384                 // 128 rows * 128B (64 fp16 / row, SW128)
#define STAGE_B (3 * TILE_B)          // A, Bhi, Blo
#define STAGES 3
#define GEMM_SMEM (STAGES * STAGE_B)  // 144 KB

__device__ __forceinline__ int sw128(int off) {
    return off ^ ((off >> 3) & 0x70);
}

__global__ __launch_bounds__(256, 1)
void gemm_kernel(const float* __restrict__ bvec, float* __restrict__ out) {
    extern __shared__ char smem[];
    const int tid = threadIdx.x;
    const int wid = tid >> 5, lane = tid & 31;
    const int m_tile = blockIdx.x >> 3;           // 256 m tiles
    const int n_tile = blockIdx.x & 7;            // 8 n tiles (inner -> A L2 reuse)
    const int m_base = m_tile * BM, n_base = n_tile * BN;
    const int warp_m = (wid & 3) * 32;            // 4 warps along m
    const int warp_n = (wid >> 2) * 64;           // 2 warps along n

    const __half* srcA  = g_yh + (size_t)m_base * DMODEL;
    const __half* srcB0 = g_wh + (size_t)n_base * DMODEL;
    const __half* srcB1 = g_wl + (size_t)n_base * DMODEL;

    // 3 tiles x 1024 16B segments = 3072 / 256 threads = 12 cp.async each
    auto load_stage = [&](int slot, int kc) {
        const int koff = kc * BK;
        char* sbase = smem + slot * STAGE_B;
        const __half* srcs[3] = { srcA + koff, srcB0 + koff, srcB1 + koff };
#pragma unroll
        for (int t = 0; t < 3; t++) {
#pragma unroll
            for (int i = 0; i < 4; i++) {
                const int seg_id = tid + i * 256;         // 0..1023
                const int row = seg_id >> 3, seg = seg_id & 7;
                const int off = sw128(row * 128 + seg * 16);
                const uint32_t dst = smem_u32(sbase + t * TILE_B + off);
                CP_ASYNC16(dst, srcs[t] + (size_t)row * DMODEL + seg * 8);
            }
        }
    };

    float acc[2][8][4];
#pragma unroll
    for (int mt = 0; mt < 2; mt++)
#pragma unroll
        for (int nt = 0; nt < 8; nt++)
#pragma unroll
            for (int i = 0; i < 4; i++) acc[mt][nt][i] = 0.0f;

    load_stage(0, 0); CP_COMMIT();
    load_stage(1, 1); CP_COMMIT();

    const int lrow = lane & 15, lhalf = lane >> 4;

#pragma unroll 1
    for (int kc = 0; kc < 16; kc++) {
        CP_WAIT1();                    // stage kc ready
        __syncthreads();               // also: everyone done reading slot (kc+2)%3
        if (kc + 2 < 16) load_stage((kc + 2) % STAGES, kc + 2);
        CP_COMMIT();                   // keep group count consistent

        const uint32_t st = smem_u32(smem + (kc % STAGES) * STAGE_B);
        const uint32_t aB  = st;
        const uint32_t bHiB = st + TILE_B, bLoB = st + 2 * TILE_B;

#pragma unroll
        for (int ks = 0; ks < 4; ks++) {
            uint32_t ah[2][4], bh4[4][4], bl4[4][4];
#pragma unroll
            for (int mt = 0; mt < 2; mt++) {
                const int row = warp_m + mt * 16 + lrow;
                const int off = sw128(row * 128 + (ks * 2 + lhalf) * 16);
                ldsm_x4(ah[mt], aB + off);
            }
#pragma unroll
            for (int np = 0; np < 4; np++) {
                const int row = warp_n + np * 16 + lrow;
                const int off = sw128(row * 128 + (ks * 2 + lhalf) * 16);
                ldsm_x4(bh4[np], bHiB + off);
                ldsm_x4(bl4[np], bLoB + off);
            }
#pragma unroll
            for (int mt = 0; mt < 2; mt++) {
#pragma unroll
                for (int nt = 0; nt < 8; nt++) {
                    const uint32_t h0 = bh4[nt >> 1][nt & 1];
                    const uint32_t h1 = bh4[nt >> 1][(nt & 1) + 2];
                    const uint32_t l0 = bl4[nt >> 1][nt & 1];
                    const uint32_t l1 = bl4[nt >> 1][(nt & 1) + 2];
                    mma_16816(acc[mt][nt], ah[mt], h0, h1);
                    mma_16816(acc[mt][nt], ah[mt], l0, l1);
                }
            }
        }
    }

    // ---- epilogue: out = acc + b[n] ----
    const int gID = lane >> 2, tig = lane & 3;
#pragma unroll
    for (int mt = 0; mt < 2; mt++) {
#pragma unroll
        for (int nt = 0; nt < 8; nt++) {
            const int n = n_base + warp_n + nt * 8 + tig * 2;
            const float b0 = bvec[n], b1 = bvec[n + 1];
            const int m0 = m_base + warp_m + mt * 16 + gID;
            float2 v0 = { acc[mt][nt][0] + b0, acc[mt][nt][1] + b1 };
            float2 v1 = { acc[mt][nt][2] + b0, acc[mt][nt][3] + b1 };
            *reinterpret_cast<float2*>(out + (size_t)m0 * DMODEL + n) = v0;
            *reinterpret_cast<float2*>(out + (size_t)(m0 + 8) * DMODEL + n) = v1;
        }
    }
}

// ---------------- launch ----------------------------------------------------
extern "C" void kernel_launch(void* const* d_in, const int* in_sizes, int n_in,
                              void* d_out, int out_size) {
    const float* x     = (const float*)d_in[0];
    const int*   ids   = (const int*)d_in[1];
    const float* gamma = (const float*)d_in[2];
    const float* beta  = (const float*)d_in[3];
    const float* scale = (const float*)d_in[4];
    const float* W     = (const float*)d_in[5];
    const float* bias  = (const float*)d_in[6];
    float* out = (float*)d_out;

    ln_split_kernel<<<NTOK, 256>>>(x, ids, gamma, beta, scale);
    wsplit_kernel<<<(DMODEL * DMODEL) / (256 * 4), 256>>>(W);

    cudaFuncSetAttribute(gemm_kernel,
                         cudaFuncAttributeMaxDynamicSharedMemorySize, GEMM_SMEM);
    gemm_kernel<<<(NTOK / BM) * (DMODEL / BN), 256, GEMM_SMEM>>>(bias, out);
}

// round 4
// speedup vs baseline: 2.8083x; 1.9210x over previous
#include <cuda_runtime.h>
#include <cuda_fp16.h>
#include <cstdint>

// Problem dims
#define NTOK   32768           // B*S = 4*8192
#define DMODEL 1024
#define NCOMP  5
#define LN_EPS 1e-5f

// ---------------- scratch (device globals; no allocation allowed) ----------
__device__ __half g_yh[(size_t)NTOK * DMODEL];   // 64 MB   y (fp16)
__device__ __half g_wh[DMODEL * DMODEL];         // 2 MB    (W + I) fp16

// ---------------- PTX helpers ----------------------------------------------
__device__ __forceinline__ uint32_t smem_u32(const void* p) {
    uint32_t a;
    asm("{ .reg .u64 t; cvta.to.shared.u64 t, %1; cvt.u32.u64 %0, t; }"
        : "=r"(a) : "l"(p));
    return a;
}

#define CP_ASYNC16(dst, src) \
    asm volatile("cp.async.cg.shared.global [%0], [%1], 16;" \
                 :: "r"(dst), "l"(src))
#define CP_COMMIT() asm volatile("cp.async.commit_group;" ::: "memory")
#define CP_WAIT1()  asm volatile("cp.async.wait_group 1;" ::: "memory")

__device__ __forceinline__ void ldsm_x4(uint32_t* r, uint32_t addr) {
    asm volatile("ldmatrix.sync.aligned.m8n8.x4.shared.b16 {%0,%1,%2,%3}, [%4];"
                 : "=r"(r[0]), "=r"(r[1]), "=r"(r[2]), "=r"(r[3]) : "r"(addr));
}

__device__ __forceinline__ void mma_16816(float* c, const uint32_t* a,
                                          uint32_t b0, uint32_t b1) {
    asm volatile(
        "mma.sync.aligned.m16n8k16.row.col.f32.f16.f16.f32 "
        "{%0,%1,%2,%3}, {%4,%5,%6,%7}, {%8,%9}, {%0,%1,%2,%3};\n"
        : "+f"(c[0]), "+f"(c[1]), "+f"(c[2]), "+f"(c[3])
        : "r"(a[0]), "r"(a[1]), "r"(a[2]), "r"(a[3]), "r"(b0), "r"(b1));
}

// ---------------- Kernel 1: warp-per-token LayerNorm + affine -> fp16 -------
// 8 warps/block, 1 token per warp. Row register-resident, shfl-only reduce.
__global__ __launch_bounds__(256)
void ln_split_kernel(const float* __restrict__ x, const int* __restrict__ ids,
                     const float* __restrict__ gamma, const float* __restrict__ beta,
                     const float* __restrict__ scale) {
    const int wid = threadIdx.x >> 5, lane = threadIdx.x & 31;
    const int token = blockIdx.x * 8 + wid;
    const float* xr = x + (size_t)token * DMODEL;

    float4 v[8];
    float s1 = 0.f, s2 = 0.f;
#pragma unroll
    for (int i = 0; i < 8; i++) {
        v[i] = *reinterpret_cast<const float4*>(xr + i * 128 + lane * 4);
        s1 += v[i].x + v[i].y + v[i].z + v[i].w;
        s2 += v[i].x * v[i].x + v[i].y * v[i].y + v[i].z * v[i].z + v[i].w * v[i].w;
    }
#pragma unroll
    for (int o = 16; o > 0; o >>= 1) {
        s1 += __shfl_xor_sync(0xffffffffu, s1, o);
        s2 += __shfl_xor_sync(0xffffffffu, s2, o);
    }
    const float mu = s1 * (1.0f / DMODEL);
    const float var = s2 * (1.0f / DMODEL) - mu * mu;
    const float rsig = rsqrtf(var + LN_EPS);

    const int cr = ids[token];
    const bool valid = (cr < NCOMP);
    const int cid = cr < 0 ? 0 : (cr >= NCOMP ? NCOMP - 1 : cr);
    const float sc = scale[cid];
    const float* gr = gamma + (size_t)cid * DMODEL;
    const float* br = beta + (size_t)cid * DMODEL;
    __half* yr = g_yh + (size_t)token * DMODEL;

#pragma unroll
    for (int i = 0; i < 8; i++) {
        const int col = i * 128 + lane * 4;
        float y0, y1, y2, y3;
        if (valid) {
            const float4 g4 = *reinterpret_cast<const float4*>(gr + col);
            const float4 b4 = *reinterpret_cast<const float4*>(br + col);
            y0 = ((v[i].x - mu) * rsig * g4.x + b4.x) * sc;
            y1 = ((v[i].y - mu) * rsig * g4.y + b4.y) * sc;
            y2 = ((v[i].z - mu) * rsig * g4.z + b4.z) * sc;
            y3 = ((v[i].w - mu) * rsig * g4.w + b4.w) * sc;
        } else {
            y0 = v[i].x; y1 = v[i].y; y2 = v[i].z; y3 = v[i].w;
        }
        __half2 p0 = __floats2half2_rn(y0, y1);
        __half2 p1 = __floats2half2_rn(y2, y3);
        uint2 pk = { *reinterpret_cast<uint32_t*>(&p0),
                     *reinterpret_cast<uint32_t*>(&p1) };
        *reinterpret_cast<uint2*>(yr + col) = pk;
    }
}

// ---------------- Kernel 2: (W + I) -> fp16 ---------------------------------
__global__ __launch_bounds__(256)
void wsplit_kernel(const float* __restrict__ W) {
    const int idx = (blockIdx.x * 256 + threadIdx.x) * 4;
    const int row = idx >> 10;          // DMODEL = 1024
    const int col = idx & 1023;
    float4 v = *reinterpret_cast<const float4*>(W + idx);
    // fold residual: out = y*W^T + y  ==  y*(W + I)^T
    if (row == col + 0) v.x += 1.0f;
    if (row == col + 1) v.y += 1.0f;
    if (row == col + 2) v.z += 1.0f;
    if (row == col + 3) v.w += 1.0f;
    __half2 p0 = __floats2half2_rn(v.x, v.y);
    __half2 p1 = __floats2half2_rn(v.z, v.w);
    uint2 pk = { *reinterpret_cast<uint32_t*>(&p0),
                 *reinterpret_cast<uint32_t*>(&p1) };
    *reinterpret_cast<uint2*>(g_wh + idx) = pk;
}

// ---------------- Kernel 3: fp16 mma.sync GEMM, out = y*(W+I)^T + b ---------
#define BM 128
#define BN 128
#define BK 64
#define TILE_B  16384                 // 128 rows * 128B (64 fp16 / row, SW128)
#define STAGE_B (2 * TILE_B)          // A, B
#define STAGES 3
#define GEMM_SMEM (STAGES * STAGE_B)  // 96 KB -> 2 CTAs/SM

__device__ __forceinline__ int sw128(int off) {
    return off ^ ((off >> 3) & 0x70);
}

__global__ __launch_bounds__(256, 2)
void gemm_kernel(const float* __restrict__ bvec, float* __restrict__ out) {
    extern __shared__ char smem[];
    const int tid = threadIdx.x;
    const int wid = tid >> 5, lane = tid & 31;
    const int m_tile = blockIdx.x >> 3;           // 256 m tiles
    const int n_tile = blockIdx.x & 7;            // 8 n tiles (inner -> A L2 reuse)
    const int m_base = m_tile * BM, n_base = n_tile * BN;
    const int warp_m = (wid & 3) * 32;            // 4 warps along m
    const int warp_n = (wid >> 2) * 64;           // 2 warps along n

    const __half* srcA = g_yh + (size_t)m_base * DMODEL;
    const __half* srcB = g_wh + (size_t)n_base * DMODEL;

    // 2 tiles x 1024 16B segments = 2048 / 256 threads = 8 cp.async each
    auto load_stage = [&](int slot, int kc) {
        const int koff = kc * BK;
        char* sbase = smem + slot * STAGE_B;
        const __half* srcs[2] = { srcA + koff, srcB + koff };
#pragma unroll
        for (int t = 0; t < 2; t++) {
#pragma unroll
            for (int i = 0; i < 4; i++) {
                const int seg_id = tid + i * 256;         // 0..1023
                const int row = seg_id >> 3, seg = seg_id & 7;
                const int off = sw128(row * 128 + seg * 16);
                const uint32_t dst = smem_u32(sbase + t * TILE_B + off);
                CP_ASYNC16(dst, srcs[t] + (size_t)row * DMODEL + seg * 8);
            }
        }
    };

    float acc[2][8][4];
#pragma unroll
    for (int mt = 0; mt < 2; mt++)
#pragma unroll
        for (int nt = 0; nt < 8; nt++)
#pragma unroll
            for (int i = 0; i < 4; i++) acc[mt][nt][i] = 0.0f;

    load_stage(0, 0); CP_COMMIT();
    load_stage(1, 1); CP_COMMIT();

    const int lrow = lane & 15, lhalf = lane >> 4;

#pragma unroll 1
    for (int kc = 0; kc < 16; kc++) {
        CP_WAIT1();                    // stage kc ready
        __syncthreads();               // everyone done reading slot (kc+2)%3
        if (kc + 2 < 16) load_stage((kc + 2) % STAGES, kc + 2);
        CP_COMMIT();                   // keep group count consistent

        const uint32_t st = smem_u32(smem + (kc % STAGES) * STAGE_B);
        const uint32_t aB = st;
        const uint32_t bB = st + TILE_B;

#pragma unroll
        for (int ks = 0; ks < 4; ks++) {
            uint32_t ah[2][4], bh4[4][4];
#pragma unroll
            for (int mt = 0; mt < 2; mt++) {
                const int row = warp_m + mt * 16 + lrow;
                const int off = sw128(row * 128 + (ks * 2 + lhalf) * 16);
                ldsm_x4(ah[mt], aB + off);
            }
#pragma unroll
            for (int np = 0; np < 4; np++) {
                const int row = warp_n + np * 16 + lrow;
                const int off = sw128(row * 128 + (ks * 2 + lhalf) * 16);
                ldsm_x4(bh4[np], bB + off);
            }
#pragma unroll
            for (int mt = 0; mt < 2; mt++) {
#pragma unroll
                for (int nt = 0; nt < 8; nt++) {
                    const uint32_t h0 = bh4[nt >> 1][nt & 1];
                    const uint32_t h1 = bh4[nt >> 1][(nt & 1) + 2];
                    mma_16816(acc[mt][nt], ah[mt], h0, h1);
                }
            }
        }
    }

    // ---- epilogue: out = acc + b[n] ----
    const int gID = lane >> 2, tig = lane & 3;
#pragma unroll
    for (int mt = 0; mt < 2; mt++) {
#pragma unroll
        for (int nt = 0; nt < 8; nt++) {
            const int n = n_base + warp_n + nt * 8 + tig * 2;
            const float b0 = bvec[n], b1 = bvec[n + 1];
            const int m0 = m_base + warp_m + mt * 16 + gID;
            float2 v0 = { acc[mt][nt][0] + b0, acc[mt][nt][1] + b1 };
            float2 v1 = { acc[mt][nt][2] + b0, acc[mt][nt][3] + b1 };
            *reinterpret_cast<float2*>(out + (size_t)m0 * DMODEL + n) = v0;
            *reinterpret_cast<float2*>(out + (size_t)(m0 + 8) * DMODEL + n) = v1;
        }
    }
}

// ---------------- launch ----------------------------------------------------
extern "C" void kernel_launch(void* const* d_in, const int* in_sizes, int n_in,
                              void* d_out, int out_size) {
    const float* x     = (const float*)d_in[0];
    const int*   ids   = (const int*)d_in[1];
    const float* gamma = (const float*)d_in[2];
    const float* beta  = (const float*)d_in[3];
    const float* scale = (const float*)d_in[4];
    const float* W     = (const float*)d_in[5];
    const float* bias  = (const float*)d_in[6];
    float* out = (float*)d_out;

    ln_split_kernel<<<NTOK / 8, 256>>>(x, ids, gamma, beta, scale);
    wsplit_kernel<<<(DMODEL * DMODEL) / (256 * 4), 256>>>(W);

    cudaFuncSetAttribute(gemm_kernel,
                         cudaFuncAttributeMaxDynamicSharedMemorySize, GEMM_SMEM);
    gemm_kernel<<<(NTOK / BM) * (DMODEL / BN), 256, GEMM_SMEM>>>(bias, out);
}